// round 10
// baseline (speedup 1.0000x reference)
#include <cuda_runtime.h>
#include <cuda_bf16.h>
#include <cstdint>
#include <math_constants.h>

constexpr int BATCH = 4, SEQ = 2048, DIM = 1024, MTOT = BATCH * SEQ;

// ---- scratch (device globals; 16B-aligned) ----
__device__ __align__(16) __nv_bfloat16 g_Xhi [(size_t)MTOT * DIM];
__device__ __align__(16) __nv_bfloat16 g_Xlo [(size_t)MTOT * DIM];
__device__ __align__(16) __nv_bfloat16 g_Wth [4][(size_t)DIM * DIM];
__device__ __align__(16) __nv_bfloat16 g_Wtl [4][(size_t)DIM * DIM];
__device__ __align__(16) __nv_bfloat16 g_Qhi [(size_t)MTOT * DIM];
__device__ __align__(16) __nv_bfloat16 g_Qlo [(size_t)MTOT * DIM];
__device__ __align__(16) __nv_bfloat16 g_Khi [(size_t)MTOT * DIM];
__device__ __align__(16) __nv_bfloat16 g_Klo [(size_t)MTOT * DIM];
__device__ __align__(16) __nv_bfloat16 g_Vthi[(size_t)BATCH * DIM * SEQ];
__device__ __align__(16) __nv_bfloat16 g_Vtlo[(size_t)BATCH * DIM * SEQ];
__device__ __align__(16) float         g_S   [(size_t)BATCH * SEQ * SEQ];
__device__ __align__(16) __nv_bfloat16 g_Phi [(size_t)BATCH * SEQ * SEQ];
__device__ __align__(16) __nv_bfloat16 g_Plo [(size_t)BATCH * SEQ * SEQ];
__device__ __align__(16) __nv_bfloat16 g_Ohi [(size_t)MTOT * DIM];
__device__ __align__(16) __nv_bfloat16 g_Olo [(size_t)MTOT * DIM];

__device__ __forceinline__ uint32_t s2u(const void* p) {
    uint32_t a;
    asm("{ .reg .u64 t; cvta.to.shared.u64 t, %1; cvt.u32.u64 %0, t; }" : "=r"(a) : "l"(p));
    return a;
}
#define CPA16(dst, src) \
    asm volatile("cp.async.cg.shared.global [%0], [%1], 16;" :: "r"(dst), "l"(src) : "memory")
#define LDSM4(r, a) \
    asm volatile("ldmatrix.sync.aligned.m8n8.x4.shared.b16 {%0,%1,%2,%3}, [%4];" \
        : "=r"((r)[0]), "=r"((r)[1]), "=r"((r)[2]), "=r"((r)[3]) : "r"(a))
#define MMA16816(c, a, b0, b1) \
    asm volatile("mma.sync.aligned.m16n8k16.row.col.f32.bf16.bf16.f32 " \
        "{%0,%1,%2,%3}, {%4,%5,%6,%7}, {%8,%9}, {%0,%1,%2,%3};" \
        : "+f"((c)[0]), "+f"((c)[1]), "+f"((c)[2]), "+f"((c)[3]) \
        : "r"((a)[0]), "r"((a)[1]), "r"((a)[2]), "r"((a)[3]), "r"(b0), "r"(b1))

// ---- GEMM: D[m][n] = sum_k A[m][k]*B[n][k]; bf16x3 split via mma.sync ----
// CTA 128x64, 4 warps (2x2), warp tile 64x32, K-chunk 16, 4-stage cp.async,
// 3 CTAs/SM for barrier overlap. ROWB=48 (conflict-free ldmatrix, proven R8).
constexpr int ROWB = 48;
constexpr int R_AH = 0, R_AL = 6144, R_BH = 12288, R_BL = 15360;
constexpr int STAGE_SZ = 18432;
constexpr int NSTAGE = 4;
constexpr int GEMM_SMEM = NSTAGE * STAGE_SZ;      // 73728

// MODE 0: fp32 out (alpha, opt bias). MODE 1: bf16 hi/lo out. MODE 2: Vt hi/lo out.
template<int MODE, bool HASBIAS>
__global__ __launch_bounds__(128, 3)
void gemm_mma(const __nv_bfloat16* __restrict__ Ah, const __nv_bfloat16* __restrict__ Al,
              const __nv_bfloat16* __restrict__ Bh, const __nv_bfloat16* __restrict__ Bl,
              float* __restrict__ Cf,
              __nv_bfloat16* __restrict__ Ch, __nv_bfloat16* __restrict__ Cl,
              const float* __restrict__ bias,
              int Kd, int ldC, float alpha,
              long long aRowZ, long long bRowZ, long long cOffZ)
{
    extern __shared__ __align__(128) char smem[];
    const uint32_t sb = s2u(smem);
    const int tid = threadIdx.x, wid = tid >> 5, lane = tid & 31;
    const int wm = wid >> 1, wn = wid & 1;          // 2x2 warp grid
    const int rowBase = blockIdx.y * 128, colBase = blockIdx.x * 64;
    const long long aRow0 = (long long)blockIdx.z * aRowZ + rowBase;
    const long long bRow0 = (long long)blockIdx.z * bRowZ + colBase;

    // cp.async: thread -> (row r=tid/2 in 0..63, granule cg=tid&1); chunk row = 32B
    const int r = tid >> 1, cg = tid & 1;
    const long long rowStep = (long long)Kd * 2;
    const char* pAH = (const char*)Ah + (aRow0 + r) * rowStep + cg * 16;
    const char* pAL = (const char*)Al + (aRow0 + r) * rowStep + cg * 16;
    const char* pBH = (const char*)Bh + (bRow0 + r) * rowStep + cg * 16;
    const char* pBL = (const char*)Bl + (bRow0 + r) * rowStep + cg * 16;
    const long long rowStep64 = 64 * rowStep;
    const uint32_t dRow = (uint32_t)(r * ROWB + cg * 16);
    const int nCh = Kd >> 4;

    auto load_stage = [&](int c, int s) {
        const uint32_t d = sb + s * STAGE_SZ + dRow;
        const long long cb = (long long)c * 32;     // 16 bf16 = 32B per chunk
        CPA16(d + R_AH,             pAH + cb);
        CPA16(d + R_AH + 64 * ROWB, pAH + rowStep64 + cb);
        CPA16(d + R_AL,             pAL + cb);
        CPA16(d + R_AL + 64 * ROWB, pAL + rowStep64 + cb);
        CPA16(d + R_BH,             pBH + cb);
        CPA16(d + R_BL,             pBL + cb);
        asm volatile("cp.async.commit_group;" ::: "memory");
    };

    // ldmatrix lane bases (R8-proven geometry; n-octet nt: pair (b[nt&1], b[(nt&1)+2]))
    const uint32_t aOff = (uint32_t)((wm * 64 + (lane & 7) + ((lane >> 3) & 1) * 8) * ROWB
                                     + (lane >> 4) * 16);
    const uint32_t bOff = (uint32_t)((wn * 32 + (lane & 7) + ((lane >> 3) & 1) * 8) * ROWB
                                     + (lane >> 4) * 16);

    float acc[4][4][4];
    #pragma unroll
    for (int i = 0; i < 4; i++)
        #pragma unroll
        for (int j = 0; j < 4; j++)
            #pragma unroll
            for (int q = 0; q < 4; q++) acc[i][j][q] = 0.0f;

    load_stage(0, 0);
    load_stage(1, 1);
    load_stage(2, 2);

    for (int c = 0; c < nCh; c++) {
        const int s = c & (NSTAGE - 1);
        const int rem = nCh - 1 - c;
        if (rem >= 2)      asm volatile("cp.async.wait_group 2;" ::: "memory");
        else if (rem == 1) asm volatile("cp.async.wait_group 1;" ::: "memory");
        else               asm volatile("cp.async.wait_group 0;" ::: "memory");
        __syncthreads();
        if (c + 3 < nCh) load_stage(c + 3, (c + 3) & (NSTAGE - 1));

        const uint32_t st = sb + s * STAGE_SZ;
        uint32_t ah[4][4], al[4][4], bh[2][4], bl[2][4];
        #pragma unroll
        for (int mt = 0; mt < 4; mt++) {
            LDSM4(ah[mt], st + R_AH + aOff + mt * (16 * ROWB));
            LDSM4(al[mt], st + R_AL + aOff + mt * (16 * ROWB));
        }
        #pragma unroll
        for (int np = 0; np < 2; np++) {
            LDSM4(bh[np], st + R_BH + bOff + np * (16 * ROWB));
            LDSM4(bl[np], st + R_BL + bOff + np * (16 * ROWB));
        }
        #pragma unroll
        for (int mt = 0; mt < 4; mt++)
            #pragma unroll
            for (int nt = 0; nt < 4; nt++) {
                const int np = nt >> 1, oc = nt & 1;
                MMA16816(acc[mt][nt], ah[mt], bh[np][oc], bh[np][oc + 2]);
            }
        #pragma unroll
        for (int mt = 0; mt < 4; mt++)
            #pragma unroll
            for (int nt = 0; nt < 4; nt++) {
                const int np = nt >> 1, oc = nt & 1;
                MMA16816(acc[mt][nt], ah[mt], bl[np][oc], bl[np][oc + 2]);
            }
        #pragma unroll
        for (int mt = 0; mt < 4; mt++)
            #pragma unroll
            for (int nt = 0; nt < 4; nt++) {
                const int np = nt >> 1, oc = nt & 1;
                MMA16816(acc[mt][nt], al[mt], bh[np][oc], bh[np][oc + 2]);
            }
    }

    // ---- epilogue ----
    if (MODE == 2) {
        // stage fragments into smem as [n][m], then coalesced 16B stores
        const int b = rowBase >> 11;
        const int seq0 = rowBase & 2047;
        const int mloc0 = wm * 64 + (lane >> 2);
        const int nloc0 = wn * 32 + (lane & 3) * 2;
        __nv_bfloat16* smt = reinterpret_cast<__nv_bfloat16*>(smem);
        constexpr int MP = 136;
        #pragma unroll 1
        for (int p = 0; p < 2; p++) {
            __syncthreads();
            #pragma unroll
            for (int mt = 0; mt < 4; mt++)
                #pragma unroll
                for (int nt = 0; nt < 4; nt++)
                    #pragma unroll
                    for (int h = 0; h < 2; h++) {
                        float v0 = acc[mt][nt][h * 2 + 0] * alpha;
                        float v1 = acc[mt][nt][h * 2 + 1] * alpha;
                        __nv_bfloat16 w0, w1;
                        if (p == 0) { w0 = __float2bfloat16(v0); w1 = __float2bfloat16(v1); }
                        else {
                            __nv_bfloat16 h0 = __float2bfloat16(v0), h1 = __float2bfloat16(v1);
                            w0 = __float2bfloat16(v0 - __bfloat162float(h0));
                            w1 = __float2bfloat16(v1 - __bfloat162float(h1));
                        }
                        const int m = mloc0 + mt * 16 + h * 8;
                        const int n = nloc0 + nt * 8;
                        smt[n * MP + m]       = w0;
                        smt[(n + 1) * MP + m] = w1;
                    }
            __syncthreads();
            __nv_bfloat16* dst = p ? Cl : Ch;
            #pragma unroll
            for (int i = 0; i < 8; i++) {
                const int g = tid + i * 128;          // 0..1023
                const int n = g >> 4, o = g & 15;     // 64 rows x 16 granules
                uint4 val = *reinterpret_cast<const uint4*>(smt + n * MP + o * 8);
                *reinterpret_cast<uint4*>(dst
                    + ((long long)(b * 1024 + colBase + n)) * 2048 + seq0 + o * 8) = val;
            }
        }
    } else {
        const int mBase = rowBase + wm * 64 + (lane >> 2);
        const int nBaseW = colBase + wn * 32 + (lane & 3) * 2;
        #pragma unroll
        for (int mt = 0; mt < 4; mt++)
            #pragma unroll
            for (int nt = 0; nt < 4; nt++) {
                const int n = nBaseW + nt * 8;
                #pragma unroll
                for (int h = 0; h < 2; h++) {
                    const int m = mBase + mt * 16 + h * 8;
                    float v0 = acc[mt][nt][h * 2 + 0] * alpha;
                    float v1 = acc[mt][nt][h * 2 + 1] * alpha;
                    if (MODE == 0) {
                        if (HASBIAS) { v0 += bias[n]; v1 += bias[n + 1]; }
                        float2 w; w.x = v0; w.y = v1;
                        *reinterpret_cast<float2*>(Cf + (long long)blockIdx.z * cOffZ
                            + (long long)m * ldC + n) = w;
                    } else {
                        __nv_bfloat16 h0 = __float2bfloat16(v0), h1 = __float2bfloat16(v1);
                        __nv_bfloat162 hp, lp;
                        hp.x = h0; hp.y = h1;
                        lp.x = __float2bfloat16(v0 - __bfloat162float(h0));
                        lp.y = __float2bfloat16(v1 - __bfloat162float(h1));
                        const long long base = (long long)blockIdx.z * cOffZ
                            + (long long)m * ldC + n;
                        *reinterpret_cast<__nv_bfloat162*>(Ch + base) = hp;
                        *reinterpret_cast<__nv_bfloat162*>(Cl + base) = lp;
                    }
                }
            }
    }
}

// ---- fp32 -> bf16 hi/lo split ----
__global__ __launch_bounds__(256)
void split_kernel(const float4* __restrict__ in, __nv_bfloat162* __restrict__ hi,
                  __nv_bfloat162* __restrict__ lo, int n4)
{
    int i = blockIdx.x * blockDim.x + threadIdx.x;
    if (i >= n4) return;
    float4 v = in[i];
    __nv_bfloat16 hx = __float2bfloat16(v.x), hy = __float2bfloat16(v.y);
    __nv_bfloat16 hz = __float2bfloat16(v.z), hw = __float2bfloat16(v.w);
    __nv_bfloat162 a, b, c, d;
    a.x = hx; a.y = hy; b.x = hz; b.y = hw;
    c.x = __float2bfloat16(v.x - __bfloat162float(hx));
    c.y = __float2bfloat16(v.y - __bfloat162float(hy));
    d.x = __float2bfloat16(v.z - __bfloat162float(hz));
    d.y = __float2bfloat16(v.w - __bfloat162float(hw));
    hi[(size_t)i*2] = a; hi[(size_t)i*2+1] = b;
    lo[(size_t)i*2] = c; lo[(size_t)i*2+1] = d;
}

// ---- all four W[1024][1024] -> Wt hi/lo (transpose + split), z selects ----
__global__ __launch_bounds__(256)
void transpose_split4(const float* __restrict__ w0, const float* __restrict__ w1,
                      const float* __restrict__ w2, const float* __restrict__ w3,
                      __nv_bfloat16* __restrict__ Th, __nv_bfloat16* __restrict__ Tl)
{
    const float* W = blockIdx.z == 0 ? w0 : blockIdx.z == 1 ? w1 : blockIdx.z == 2 ? w2 : w3;
    __nv_bfloat16* oh = Th + (size_t)blockIdx.z * DIM * DIM;
    __nv_bfloat16* ol = Tl + (size_t)blockIdx.z * DIM * DIM;
    __shared__ float t[32][33];
    int x = blockIdx.x * 32 + threadIdx.x;
    int y0 = blockIdx.y * 32;
    #pragma unroll
    for (int j = threadIdx.y; j < 32; j += 8)
        t[j][threadIdx.x] = W[(long long)(y0 + j) * DIM + x];
    __syncthreads();
    int xo = y0 + threadIdx.x, yo = blockIdx.x * 32;
    #pragma unroll
    for (int j = threadIdx.y; j < 32; j += 8) {
        float v = t[threadIdx.x][j];
        __nv_bfloat16 h = __float2bfloat16(v);
        long long idx = (long long)(yo + j) * DIM + xo;
        oh[idx] = h;
        ol[idx] = __float2bfloat16(v - __bfloat162float(h));
    }
}

// ---- softmax over 2048 cols + bf16 hi/lo split of P ----
__global__ __launch_bounds__(256)
void softmax_split_kernel(const float* __restrict__ S,
                          __nv_bfloat16* __restrict__ Ph, __nv_bfloat16* __restrict__ Pl)
{
    const float* row = S + (long long)blockIdx.x * SEQ;
    const int tid = threadIdx.x;
    float v[8], m = -CUDART_INF_F;
    #pragma unroll
    for (int i = 0; i < 8; i++) { v[i] = row[tid + i*256]; m = fmaxf(m, v[i]); }
    __shared__ float red[256];
    red[tid] = m; __syncthreads();
    #pragma unroll
    for (int s = 128; s > 0; s >>= 1) { if (tid < s) red[tid] = fmaxf(red[tid], red[tid+s]); __syncthreads(); }
    m = red[0]; __syncthreads();
    float sum = 0.f;
    #pragma unroll
    for (int i = 0; i < 8; i++) { v[i] = __expf(v[i] - m); sum += v[i]; }
    red[tid] = sum; __syncthreads();
    #pragma unroll
    for (int s = 128; s > 0; s >>= 1) { if (tid < s) red[tid] += red[tid+s]; __syncthreads(); }
    float inv = 1.0f / red[0];
    const long long base = (long long)blockIdx.x * SEQ;
    #pragma unroll
    for (int i = 0; i < 8; i++) {
        float p = v[i] * inv;
        __nv_bfloat16 h = __float2bfloat16(p);
        Ph[base + tid + i*256] = h;
        Pl[base + tid + i*256] = __float2bfloat16(p - __bfloat162float(h));
    }
}

// ---- launch ----
extern "C" void kernel_launch(void* const* d_in, const int* in_sizes, int n_in,
                              void* d_out, int out_size)
{
    const float* X  = (const float*)d_in[0];
    const float* bo = (const float*)d_in[5];
    float* out = (float*)d_out;

    __nv_bfloat16 *Xhi, *Xlo, *Qhi, *Qlo, *Khi, *Klo, *Vthi, *Vtlo, *Phi, *Plo, *Ohi, *Olo;
    __nv_bfloat16 *Wth, *Wtl;
    float* Sc;
    cudaGetSymbolAddress((void**)&Xhi, g_Xhi);   cudaGetSymbolAddress((void**)&Xlo, g_Xlo);
    cudaGetSymbolAddress((void**)&Wth, g_Wth);   cudaGetSymbolAddress((void**)&Wtl, g_Wtl);
    cudaGetSymbolAddress((void**)&Qhi, g_Qhi);   cudaGetSymbolAddress((void**)&Qlo, g_Qlo);
    cudaGetSymbolAddress((void**)&Khi, g_Khi);   cudaGetSymbolAddress((void**)&Klo, g_Klo);
    cudaGetSymbolAddress((void**)&Vthi, g_Vthi); cudaGetSymbolAddress((void**)&Vtlo, g_Vtlo);
    cudaGetSymbolAddress((void**)&Sc, g_S);
    cudaGetSymbolAddress((void**)&Phi, g_Phi);   cudaGetSymbolAddress((void**)&Plo, g_Plo);
    cudaGetSymbolAddress((void**)&Ohi, g_Ohi);   cudaGetSymbolAddress((void**)&Olo, g_Olo);

    cudaFuncSetAttribute(gemm_mma<0,false>, cudaFuncAttributeMaxDynamicSharedMemorySize, GEMM_SMEM);
    cudaFuncSetAttribute(gemm_mma<0,true >, cudaFuncAttributeMaxDynamicSharedMemorySize, GEMM_SMEM);
    cudaFuncSetAttribute(gemm_mma<1,false>, cudaFuncAttributeMaxDynamicSharedMemorySize, GEMM_SMEM);
    cudaFuncSetAttribute(gemm_mma<2,false>, cudaFuncAttributeMaxDynamicSharedMemorySize, GEMM_SMEM);

    const size_t wsz = (size_t)DIM * DIM;

    // 1: X split   2: W transpose+split
    split_kernel<<<(MTOT*DIM/4 + 255)/256, 256>>>((const float4*)X,
        (__nv_bfloat162*)Xhi, (__nv_bfloat162*)Xlo, MTOT*DIM/4);
    transpose_split4<<<dim3(32,32,4), dim3(32,8)>>>((const float*)d_in[1], (const float*)d_in[2],
        (const float*)d_in[3], (const float*)d_in[4], Wth, Wtl);

    // 3-5: Q, K, Vt projections
    {
        dim3 g(DIM/64, MTOT/128, 1);
        gemm_mma<1,false><<<g, 128, GEMM_SMEM>>>(Xhi, Xlo, Wth + 0*wsz, Wtl + 0*wsz,
            nullptr, Qhi, Qlo, nullptr, DIM, DIM, 1.0f, 0, 0, 0);
        gemm_mma<1,false><<<g, 128, GEMM_SMEM>>>(Xhi, Xlo, Wth + 1*wsz, Wtl + 1*wsz,
            nullptr, Khi, Klo, nullptr, DIM, DIM, 1.0f, 0, 0, 0);
        gemm_mma<2,false><<<g, 128, GEMM_SMEM>>>(Xhi, Xlo, Wth + 2*wsz, Wtl + 2*wsz,
            nullptr, Vthi, Vtlo, nullptr, DIM, DIM, 1.0f, 0, 0, 0);
    }

    // 6: scores = (Q @ K^T)/32  (captured by ncu -s 5 -c 1)
    {
        dim3 g(SEQ/64, SEQ/128, BATCH);
        gemm_mma<0,false><<<g, 128, GEMM_SMEM>>>(Qhi, Qlo, Khi, Klo,
            Sc, nullptr, nullptr, nullptr, DIM, SEQ, 1.0f/32.0f,
            (long long)SEQ, (long long)SEQ, (long long)SEQ * SEQ);
    }

    // 7: softmax + split -> P hi/lo
    softmax_split_kernel<<<BATCH*SEQ, 256>>>(Sc, Phi, Plo);

    // 8: O = P @ V  (B = Vt K-major, K=2048)
    {
        dim3 g(DIM/64, SEQ/128, BATCH);
        gemm_mma<1,false><<<g, 128, GEMM_SMEM>>>(Phi, Plo, Vthi, Vtlo,
            nullptr, Ohi, Olo, nullptr, SEQ, DIM, 1.0f,
            (long long)SEQ, (long long)DIM, (long long)SEQ * DIM);
    }

    // 9: out = O @ Wo + bo
    {
        dim3 g(DIM/64, MTOT/128, 1);
        gemm_mma<0,true><<<g, 128, GEMM_SMEM>>>(Ohi, Olo, Wth + 3*wsz, Wtl + 3*wsz,
            out, nullptr, nullptr, bo, DIM, DIM, 1.0f, 0, 0, 0);
    }
}

// round 11
// speedup vs baseline: 1.2187x; 1.2187x over previous
#include <cuda_runtime.h>
#include <cuda_bf16.h>
#include <cstdint>
#include <math_constants.h>

constexpr int BATCH = 4, SEQ = 2048, DIM = 1024, MTOT = BATCH * SEQ;

// ---- scratch (device globals; 16B-aligned) ----
__device__ __align__(16) __nv_bfloat16 g_Xhi [(size_t)MTOT * DIM];
__device__ __align__(16) __nv_bfloat16 g_Xlo [(size_t)MTOT * DIM];
__device__ __align__(16) __nv_bfloat16 g_Wth [4][(size_t)DIM * DIM];
__device__ __align__(16) __nv_bfloat16 g_Wtl [4][(size_t)DIM * DIM];
__device__ __align__(16) __nv_bfloat16 g_Qhi [(size_t)MTOT * DIM];
__device__ __align__(16) __nv_bfloat16 g_Qlo [(size_t)MTOT * DIM];
__device__ __align__(16) __nv_bfloat16 g_Khi [(size_t)MTOT * DIM];
__device__ __align__(16) __nv_bfloat16 g_Klo [(size_t)MTOT * DIM];
__device__ __align__(16) __nv_bfloat16 g_Vthi[(size_t)BATCH * DIM * SEQ];
__device__ __align__(16) __nv_bfloat16 g_Vtlo[(size_t)BATCH * DIM * SEQ];
__device__ __align__(16) float         g_S   [(size_t)BATCH * SEQ * SEQ];
__device__ __align__(16) __nv_bfloat16 g_Phi [(size_t)BATCH * SEQ * SEQ];
__device__ __align__(16) __nv_bfloat16 g_Plo [(size_t)BATCH * SEQ * SEQ];
__device__ __align__(16) __nv_bfloat16 g_Ohi [(size_t)MTOT * DIM];
__device__ __align__(16) __nv_bfloat16 g_Olo [(size_t)MTOT * DIM];

__device__ __forceinline__ uint32_t s2u(const void* p) {
    uint32_t a;
    asm("{ .reg .u64 t; cvta.to.shared.u64 t, %1; cvt.u32.u64 %0, t; }" : "=r"(a) : "l"(p));
    return a;
}
#define CPA16(dst, src) \
    asm volatile("cp.async.cg.shared.global [%0], [%1], 16;" :: "r"(dst), "l"(src) : "memory")
#define LDSM4(r, a) \
    asm volatile("ldmatrix.sync.aligned.m8n8.x4.shared.b16 {%0,%1,%2,%3}, [%4];" \
        : "=r"((r)[0]), "=r"((r)[1]), "=r"((r)[2]), "=r"((r)[3]) : "r"(a))
#define MMA16816(c, a, b0, b1) \
    asm volatile("mma.sync.aligned.m16n8k16.row.col.f32.bf16.bf16.f32 " \
        "{%0,%1,%2,%3}, {%4,%5,%6,%7}, {%8,%9}, {%0,%1,%2,%3};" \
        : "+f"((c)[0]), "+f"((c)[1]), "+f"((c)[2]), "+f"((c)[3]) \
        : "r"((a)[0]), "r"((a)[1]), "r"((a)[2]), "r"((a)[3]), "r"(b0), "r"(b1))

// ---- GEMM: D[m][n] = sum_k A[m][k]*B[n][k]; bf16x3 split via mma.sync ----
// CTA 128x128, 8 warps (2x4), warp tile 64x32, K-chunk 32, 5-stage cp.async,
// TWO stages consumed per barrier (one __syncthreads per 64 K).
// SMEM rows padded to 80B (conflict-free ldmatrix).
constexpr int ROWB = 80;
constexpr int R_AH = 0, R_AL = 10240, R_BH = 20480, R_BL = 30720;
constexpr int STAGE_SZ = 40960;
constexpr int NSTAGE = 5;
constexpr int GEMM_SMEM = NSTAGE * STAGE_SZ;      // 204800

// MODE 0: fp32 out (alpha, opt bias). MODE 1: bf16 hi/lo out. MODE 2: Vt hi/lo out.
template<int MODE, bool HASBIAS>
__global__ __launch_bounds__(256, 1)
void gemm_mma(const __nv_bfloat16* __restrict__ Ah, const __nv_bfloat16* __restrict__ Al,
              const __nv_bfloat16* __restrict__ Bh, const __nv_bfloat16* __restrict__ Bl,
              float* __restrict__ Cf,
              __nv_bfloat16* __restrict__ Ch, __nv_bfloat16* __restrict__ Cl,
              const float* __restrict__ bias,
              int Kd, int ldC, float alpha,
              long long aRowZ, long long bRowZ, long long cOffZ)
{
    extern __shared__ __align__(128) char smem[];
    const uint32_t sb = s2u(smem);
    const int tid = threadIdx.x, wid = tid >> 5, lane = tid & 31;
    const int wm = wid >> 2, wn = wid & 3;
    const int rowBase = blockIdx.y * 128, colBase = blockIdx.x * 128;
    const long long aRow0 = (long long)blockIdx.z * aRowZ + rowBase;
    const long long bRow0 = (long long)blockIdx.z * bRowZ + colBase;

    // cp.async geometry: thread -> (row r=tid/4 in 0..63, granule cg=tid&3)
    const int r = tid >> 2, cg = tid & 3;
    const long long rowStep = (long long)Kd * 2;
    const char* pAH = (const char*)Ah + (aRow0 + r) * rowStep + cg * 16;
    const char* pAL = (const char*)Al + (aRow0 + r) * rowStep + cg * 16;
    const char* pBH = (const char*)Bh + (bRow0 + r) * rowStep + cg * 16;
    const char* pBL = (const char*)Bl + (bRow0 + r) * rowStep + cg * 16;
    const uint32_t dRow = (uint32_t)(r * ROWB + cg * 16);
    const long long rowStep64 = 64 * rowStep;
    const int nCh = Kd >> 5;          // K-chunks of 32 (always even here)

    auto load_stage = [&](int c, int s) {
        const uint32_t d = sb + s * STAGE_SZ + dRow;
        const long long cb = (long long)c * 64;
        #pragma unroll
        for (int i = 0; i < 2; i++) {
            CPA16(d + R_AH + i * 64 * ROWB, pAH + i * rowStep64 + cb);
            CPA16(d + R_AL + i * 64 * ROWB, pAL + i * rowStep64 + cb);
            CPA16(d + R_BH + i * 64 * ROWB, pBH + i * rowStep64 + cb);
            CPA16(d + R_BL + i * 64 * ROWB, pBL + i * rowStep64 + cb);
        }
        asm volatile("cp.async.commit_group;" ::: "memory");
    };

    const uint32_t aOff = (uint32_t)((wm * 64 + (lane & 7) + ((lane >> 3) & 1) * 8) * ROWB
                                     + ((lane >> 4) * 8) * 2);
    const uint32_t bOff = (uint32_t)((wn * 32 + (lane & 7) + ((lane >> 4) & 1) * 8) * ROWB
                                     + (((lane >> 3) & 1) * 8) * 2);

    float acc[4][4][4];
    #pragma unroll
    for (int i = 0; i < 4; i++)
        #pragma unroll
        for (int j = 0; j < 4; j++)
            #pragma unroll
            for (int q = 0; q < 4; q++) acc[i][j][q] = 0.0f;

    // prolog: chunks 0,1,2 -> stages 0,1,2 (chunk c always lives in stage c mod 5)
    load_stage(0, 0);
    load_stage(1, 1);
    load_stage(2, 2);

    int nc = 3, ps = 3;      // next chunk to prefetch and its stage
    int cs = 0;              // stage of chunk cc

    for (int cc = 0; cc < nCh; cc += 2) {
        // need chunks cc, cc+1 complete; newest commit is chunk cc+2 (if it exists)
        if (cc + 2 < nCh) asm volatile("cp.async.wait_group 1;" ::: "memory");
        else              asm volatile("cp.async.wait_group 0;" ::: "memory");
        __syncthreads();
        // refill the two stages freed by the previous iteration
        #pragma unroll
        for (int j = 0; j < 2; j++) {
            if (nc < nCh) {
                load_stage(nc, ps);
                nc++;
                ps = (ps == NSTAGE - 1) ? 0 : ps + 1;
            }
        }

        #pragma unroll
        for (int half = 0; half < 2; half++) {
            const uint32_t st = sb + cs * STAGE_SZ;
            #pragma unroll
            for (int k16 = 0; k16 < 2; k16++) {
                uint32_t ah[4][4], al[4][4], bh[2][4], bl[2][4];
                #pragma unroll
                for (int mt = 0; mt < 4; mt++) {
                    LDSM4(ah[mt], st + R_AH + aOff + mt * (16 * ROWB) + k16 * 32);
                    LDSM4(al[mt], st + R_AL + aOff + mt * (16 * ROWB) + k16 * 32);
                }
                #pragma unroll
                for (int j = 0; j < 2; j++) {
                    LDSM4(bh[j], st + R_BH + bOff + j * (16 * ROWB) + k16 * 32);
                    LDSM4(bl[j], st + R_BL + bOff + j * (16 * ROWB) + k16 * 32);
                }
                #pragma unroll
                for (int mt = 0; mt < 4; mt++)
                    #pragma unroll
                    for (int nt = 0; nt < 4; nt++) {
                        const int jj = nt >> 1, hh = (nt & 1) * 2;
                        MMA16816(acc[mt][nt], ah[mt], bh[jj][hh], bh[jj][hh + 1]);
                    }
                #pragma unroll
                for (int mt = 0; mt < 4; mt++)
                    #pragma unroll
                    for (int nt = 0; nt < 4; nt++) {
                        const int jj = nt >> 1, hh = (nt & 1) * 2;
                        MMA16816(acc[mt][nt], ah[mt], bl[jj][hh], bl[jj][hh + 1]);
                    }
                #pragma unroll
                for (int mt = 0; mt < 4; mt++)
                    #pragma unroll
                    for (int nt = 0; nt < 4; nt++) {
                        const int jj = nt >> 1, hh = (nt & 1) * 2;
                        MMA16816(acc[mt][nt], al[mt], bh[jj][hh], bh[jj][hh + 1]);
                    }
            }
            cs = (cs == NSTAGE - 1) ? 0 : cs + 1;
        }
    }

    // ---- epilogue (identical to round 6) ----
    if (MODE == 2) {
        const int b = rowBase >> 11;
        const int seq0 = rowBase & 2047;
        const int mloc0 = wm * 64 + (lane >> 2);
        const int nloc0 = wn * 32 + (lane & 3) * 2;
        __nv_bfloat16* smt = reinterpret_cast<__nv_bfloat16*>(smem);
        constexpr int MP = 136;
        #pragma unroll 1
        for (int p = 0; p < 2; p++) {
            __syncthreads();
            #pragma unroll
            for (int mt = 0; mt < 4; mt++)
                #pragma unroll
                for (int nt = 0; nt < 4; nt++)
                    #pragma unroll
                    for (int h = 0; h < 2; h++) {
                        float v0 = acc[mt][nt][h * 2 + 0] * alpha;
                        float v1 = acc[mt][nt][h * 2 + 1] * alpha;
                        __nv_bfloat16 w0, w1;
                        if (p == 0) { w0 = __float2bfloat16(v0); w1 = __float2bfloat16(v1); }
                        else {
                            __nv_bfloat16 h0 = __float2bfloat16(v0), h1 = __float2bfloat16(v1);
                            w0 = __float2bfloat16(v0 - __bfloat162float(h0));
                            w1 = __float2bfloat16(v1 - __bfloat162float(h1));
                        }
                        const int m = mloc0 + mt * 16 + h * 8;
                        const int n = nloc0 + nt * 8;
                        smt[n * MP + m]       = w0;
                        smt[(n + 1) * MP + m] = w1;
                    }
            __syncthreads();
            __nv_bfloat16* dst = p ? Cl : Ch;
            #pragma unroll
            for (int i = 0; i < 8; i++) {
                const int g = tid + i * 256;
                const int n = g >> 4, o = g & 15;
                uint4 val = *reinterpret_cast<const uint4*>(smt + n * MP + o * 8);
                *reinterpret_cast<uint4*>(dst
                    + ((long long)(b * 1024 + colBase + n)) * 2048 + seq0 + o * 8) = val;
            }
        }
    } else {
        const int mBase = rowBase + wm * 64 + (lane >> 2);
        const int nBaseW = colBase + wn * 32 + (lane & 3) * 2;
        #pragma unroll
        for (int mt = 0; mt < 4; mt++)
            #pragma unroll
            for (int nt = 0; nt < 4; nt++) {
                const int n = nBaseW + nt * 8;
                #pragma unroll
                for (int h = 0; h < 2; h++) {
                    const int m = mBase + mt * 16 + h * 8;
                    float v0 = acc[mt][nt][h * 2 + 0] * alpha;
                    float v1 = acc[mt][nt][h * 2 + 1] * alpha;
                    if (MODE == 0) {
                        if (HASBIAS) { v0 += bias[n]; v1 += bias[n + 1]; }
                        float2 w; w.x = v0; w.y = v1;
                        *reinterpret_cast<float2*>(Cf + (long long)blockIdx.z * cOffZ
                            + (long long)m * ldC + n) = w;
                    } else {
                        __nv_bfloat16 h0 = __float2bfloat16(v0), h1 = __float2bfloat16(v1);
                        __nv_bfloat162 hp, lp;
                        hp.x = h0; hp.y = h1;
                        lp.x = __float2bfloat16(v0 - __bfloat162float(h0));
                        lp.y = __float2bfloat16(v1 - __bfloat162float(h1));
                        const long long base = (long long)blockIdx.z * cOffZ
                            + (long long)m * ldC + n;
                        *reinterpret_cast<__nv_bfloat162*>(Ch + base) = hp;
                        *reinterpret_cast<__nv_bfloat162*>(Cl + base) = lp;
                    }
                }
            }
    }
}

// ---- fp32 -> bf16 hi/lo split ----
__global__ __launch_bounds__(256)
void split_kernel(const float4* __restrict__ in, __nv_bfloat162* __restrict__ hi,
                  __nv_bfloat162* __restrict__ lo, int n4)
{
    int i = blockIdx.x * blockDim.x + threadIdx.x;
    if (i >= n4) return;
    float4 v = in[i];
    __nv_bfloat16 hx = __float2bfloat16(v.x), hy = __float2bfloat16(v.y);
    __nv_bfloat16 hz = __float2bfloat16(v.z), hw = __float2bfloat16(v.w);
    __nv_bfloat162 a, b, c, d;
    a.x = hx; a.y = hy; b.x = hz; b.y = hw;
    c.x = __float2bfloat16(v.x - __bfloat162float(hx));
    c.y = __float2bfloat16(v.y - __bfloat162float(hy));
    d.x = __float2bfloat16(v.z - __bfloat162float(hz));
    d.y = __float2bfloat16(v.w - __bfloat162float(hw));
    hi[(size_t)i*2] = a; hi[(size_t)i*2+1] = b;
    lo[(size_t)i*2] = c; lo[(size_t)i*2+1] = d;
}

// ---- all four W[1024][1024] -> Wt hi/lo (transpose + split), z selects ----
__global__ __launch_bounds__(256)
void transpose_split4(const float* __restrict__ w0, const float* __restrict__ w1,
                      const float* __restrict__ w2, const float* __restrict__ w3,
                      __nv_bfloat16* __restrict__ Th, __nv_bfloat16* __restrict__ Tl)
{
    const float* W = blockIdx.z == 0 ? w0 : blockIdx.z == 1 ? w1 : blockIdx.z == 2 ? w2 : w3;
    __nv_bfloat16* oh = Th + (size_t)blockIdx.z * DIM * DIM;
    __nv_bfloat16* ol = Tl + (size_t)blockIdx.z * DIM * DIM;
    __shared__ float t[32][33];
    int x = blockIdx.x * 32 + threadIdx.x;
    int y0 = blockIdx.y * 32;
    #pragma unroll
    for (int j = threadIdx.y; j < 32; j += 8)
        t[j][threadIdx.x] = W[(long long)(y0 + j) * DIM + x];
    __syncthreads();
    int xo = y0 + threadIdx.x, yo = blockIdx.x * 32;
    #pragma unroll
    for (int j = threadIdx.y; j < 32; j += 8) {
        float v = t[threadIdx.x][j];
        __nv_bfloat16 h = __float2bfloat16(v);
        long long idx = (long long)(yo + j) * DIM + xo;
        oh[idx] = h;
        ol[idx] = __float2bfloat16(v - __bfloat162float(h));
    }
}

// ---- softmax over 2048 cols + bf16 hi/lo split of P ----
__global__ __launch_bounds__(256)
void softmax_split_kernel(const float* __restrict__ S,
                          __nv_bfloat16* __restrict__ Ph, __nv_bfloat16* __restrict__ Pl)
{
    const float* row = S + (long long)blockIdx.x * SEQ;
    const int tid = threadIdx.x;
    float v[8], m = -CUDART_INF_F;
    #pragma unroll
    for (int i = 0; i < 8; i++) { v[i] = row[tid + i*256]; m = fmaxf(m, v[i]); }
    __shared__ float red[256];
    red[tid] = m; __syncthreads();
    #pragma unroll
    for (int s = 128; s > 0; s >>= 1) { if (tid < s) red[tid] = fmaxf(red[tid], red[tid+s]); __syncthreads(); }
    m = red[0]; __syncthreads();
    float sum = 0.f;
    #pragma unroll
    for (int i = 0; i < 8; i++) { v[i] = __expf(v[i] - m); sum += v[i]; }
    red[tid] = sum; __syncthreads();
    #pragma unroll
    for (int s = 128; s > 0; s >>= 1) { if (tid < s) red[tid] += red[tid+s]; __syncthreads(); }
    float inv = 1.0f / red[0];
    const long long base = (long long)blockIdx.x * SEQ;
    #pragma unroll
    for (int i = 0; i < 8; i++) {
        float p = v[i] * inv;
        __nv_bfloat16 h = __float2bfloat16(p);
        Ph[base + tid + i*256] = h;
        Pl[base + tid + i*256] = __float2bfloat16(p - __bfloat162float(h));
    }
}

// ---- launch ----
extern "C" void kernel_launch(void* const* d_in, const int* in_sizes, int n_in,
                              void* d_out, int out_size)
{
    const float* X  = (const float*)d_in[0];
    const float* bo = (const float*)d_in[5];
    float* out = (float*)d_out;

    __nv_bfloat16 *Xhi, *Xlo, *Qhi, *Qlo, *Khi, *Klo, *Vthi, *Vtlo, *Phi, *Plo, *Ohi, *Olo;
    __nv_bfloat16 *Wth, *Wtl;
    float* Sc;
    cudaGetSymbolAddress((void**)&Xhi, g_Xhi);   cudaGetSymbolAddress((void**)&Xlo, g_Xlo);
    cudaGetSymbolAddress((void**)&Wth, g_Wth);   cudaGetSymbolAddress((void**)&Wtl, g_Wtl);
    cudaGetSymbolAddress((void**)&Qhi, g_Qhi);   cudaGetSymbolAddress((void**)&Qlo, g_Qlo);
    cudaGetSymbolAddress((void**)&Khi, g_Khi);   cudaGetSymbolAddress((void**)&Klo, g_Klo);
    cudaGetSymbolAddress((void**)&Vthi, g_Vthi); cudaGetSymbolAddress((void**)&Vtlo, g_Vtlo);
    cudaGetSymbolAddress((void**)&Sc, g_S);
    cudaGetSymbolAddress((void**)&Phi, g_Phi);   cudaGetSymbolAddress((void**)&Plo, g_Plo);
    cudaGetSymbolAddress((void**)&Ohi, g_Ohi);   cudaGetSymbolAddress((void**)&Olo, g_Olo);

    cudaFuncSetAttribute(gemm_mma<0,false>, cudaFuncAttributeMaxDynamicSharedMemorySize, GEMM_SMEM);
    cudaFuncSetAttribute(gemm_mma<0,true >, cudaFuncAttributeMaxDynamicSharedMemorySize, GEMM_SMEM);
    cudaFuncSetAttribute(gemm_mma<1,false>, cudaFuncAttributeMaxDynamicSharedMemorySize, GEMM_SMEM);
    cudaFuncSetAttribute(gemm_mma<2,false>, cudaFuncAttributeMaxDynamicSharedMemorySize, GEMM_SMEM);

    const size_t wsz = (size_t)DIM * DIM;

    // 1: X split   2: W transpose+split
    split_kernel<<<(MTOT*DIM/4 + 255)/256, 256>>>((const float4*)X,
        (__nv_bfloat162*)Xhi, (__nv_bfloat162*)Xlo, MTOT*DIM/4);
    transpose_split4<<<dim3(32,32,4), dim3(32,8)>>>((const float*)d_in[1], (const float*)d_in[2],
        (const float*)d_in[3], (const float*)d_in[4], Wth, Wtl);

    // 3-5: Q, K, Vt projections
    {
        dim3 g(DIM/128, MTOT/128, 1);
        gemm_mma<1,false><<<g, 256, GEMM_SMEM>>>(Xhi, Xlo, Wth + 0*wsz, Wtl + 0*wsz,
            nullptr, Qhi, Qlo, nullptr, DIM, DIM, 1.0f, 0, 0, 0);
        gemm_mma<1,false><<<g, 256, GEMM_SMEM>>>(Xhi, Xlo, Wth + 1*wsz, Wtl + 1*wsz,
            nullptr, Khi, Klo, nullptr, DIM, DIM, 1.0f, 0, 0, 0);
        gemm_mma<2,false><<<g, 256, GEMM_SMEM>>>(Xhi, Xlo, Wth + 2*wsz, Wtl + 2*wsz,
            nullptr, Vthi, Vtlo, nullptr, DIM, DIM, 1.0f, 0, 0, 0);
    }

    // 6: scores = (Q @ K^T)/32  (captured by ncu -s 5 -c 1)
    {
        dim3 g(SEQ/128, SEQ/128, BATCH);
        gemm_mma<0,false><<<g, 256, GEMM_SMEM>>>(Qhi, Qlo, Khi, Klo,
            Sc, nullptr, nullptr, nullptr, DIM, SEQ, 1.0f/32.0f,
            (long long)SEQ, (long long)SEQ, (long long)SEQ * SEQ);
    }

    // 7: softmax + split -> P hi/lo
    softmax_split_kernel<<<BATCH*SEQ, 256>>>(Sc, Phi, Plo);

    // 8: O = P @ V  (B = Vt K-major, K=2048)
    {
        dim3 g(DIM/128, SEQ/128, BATCH);
        gemm_mma<1,false><<<g, 256, GEMM_SMEM>>>(Phi, Plo, Vthi, Vtlo,
            nullptr, Ohi, Olo, nullptr, SEQ, DIM, 1.0f,
            (long long)SEQ, (long long)DIM, (long long)SEQ * DIM);
    }

    // 9: out = O @ Wo + bo
    {
        dim3 g(DIM/128, MTOT/128, 1);
        gemm_mma<0,true><<<g, 256, GEMM_SMEM>>>(Ohi, Olo, Wth + 3*wsz, Wtl + 3*wsz,
            out, nullptr, nullptr, bo, DIM, DIM, 1.0f, 0, 0, 0);
    }
}